// round 1
// baseline (speedup 1.0000x reference)
#include <cuda_runtime.h>
#include <math.h>

// Problem constants
#define Bc 2
#define Tc 2048
#define Cc 1024
#define Hc 16
#define HDc 64
#define M_ROWS (Bc * Tc)            // 4096
#define QKV_COLS (3 * Cc)           // 3072

// Scratch (device globals: no allocation allowed in kernel_launch)
__device__ float g_qkv[(size_t)M_ROWS * QKV_COLS];   // [B*T, 3C]
__device__ float g_y[(size_t)M_ROWS * Cc];           // [B*T, C] attention output

// ---------------------------------------------------------------------------
// SGEMM: C[m,n] = sum_k A[m,k] * W[n,k] + bias[n]
// A: [M,K] row-major, W: [N,K] row-major (torch Linear weight), C: [M,N]
// Tile 128x128x8, 256 threads, 8x8 per-thread micro-tile.
// M,N,K must be multiples of 128/128/8 (true for all our shapes).
// ---------------------------------------------------------------------------
#define BM 128
#define BN 128
#define BKK 8

__global__ __launch_bounds__(256) void sgemm_nt_bias(
    const float* __restrict__ A, const float* __restrict__ W,
    const float* __restrict__ bias, float* __restrict__ C,
    int M, int N, int K)
{
    __shared__ float As[BKK][BM];
    __shared__ float Bs[BKK][BN];

    const int tid = threadIdx.x;
    const int brow = blockIdx.y * BM;
    const int bcol = blockIdx.x * BN;
    const int ty = tid >> 4;          // 0..15
    const int tx = tid & 15;          // 0..15

    // Loader mapping: each thread loads one float4 of A and one of W per k-step
    const int lr = tid >> 1;          // 0..127 (row within tile)
    const int lc = (tid & 1) * 4;     // 0 or 4 (k offset)

    const float* Aptr = A + (size_t)(brow + lr) * K + lc;
    const float* Wptr = W + (size_t)(bcol + lr) * K + lc;

    float acc[8][8];
#pragma unroll
    for (int i = 0; i < 8; i++)
#pragma unroll
        for (int j = 0; j < 8; j++) acc[i][j] = 0.0f;

    for (int k0 = 0; k0 < K; k0 += BKK) {
        float4 a4 = *(const float4*)(Aptr + k0);
        float4 w4 = *(const float4*)(Wptr + k0);
        As[lc + 0][lr] = a4.x; As[lc + 1][lr] = a4.y;
        As[lc + 2][lr] = a4.z; As[lc + 3][lr] = a4.w;
        Bs[lc + 0][lr] = w4.x; Bs[lc + 1][lr] = w4.y;
        Bs[lc + 2][lr] = w4.z; Bs[lc + 3][lr] = w4.w;
        __syncthreads();

#pragma unroll
        for (int k = 0; k < BKK; k++) {
            float ar[8], br[8];
            float4 a0 = *(const float4*)(&As[k][ty * 8]);
            float4 a1 = *(const float4*)(&As[k][ty * 8 + 4]);
            float4 b0 = *(const float4*)(&Bs[k][tx * 8]);
            float4 b1 = *(const float4*)(&Bs[k][tx * 8 + 4]);
            ar[0] = a0.x; ar[1] = a0.y; ar[2] = a0.z; ar[3] = a0.w;
            ar[4] = a1.x; ar[5] = a1.y; ar[6] = a1.z; ar[7] = a1.w;
            br[0] = b0.x; br[1] = b0.y; br[2] = b0.z; br[3] = b0.w;
            br[4] = b1.x; br[5] = b1.y; br[6] = b1.z; br[7] = b1.w;
#pragma unroll
            for (int i = 0; i < 8; i++)
#pragma unroll
                for (int j = 0; j < 8; j++)
                    acc[i][j] += ar[i] * br[j];
        }
        __syncthreads();
    }

    // Epilogue with bias
#pragma unroll
    for (int i = 0; i < 8; i++) {
        float* Crow = C + (size_t)(brow + ty * 8 + i) * N + bcol + tx * 8;
#pragma unroll
        for (int j = 0; j < 8; j += 4) {
            float4 o;
            o.x = acc[i][j + 0] + bias[bcol + tx * 8 + j + 0];
            o.y = acc[i][j + 1] + bias[bcol + tx * 8 + j + 1];
            o.z = acc[i][j + 2] + bias[bcol + tx * 8 + j + 2];
            o.w = acc[i][j + 3] + bias[bcol + tx * 8 + j + 3];
            *(float4*)(Crow + j) = o;
        }
    }
}

// ---------------------------------------------------------------------------
// Flash attention (causal), fp32, one thread per query row.
// Block: 128 threads = 128 query rows. Grid: (B*H, T/128).
// K/V tiles of 32 rows staged in smem (broadcast reads).
// ---------------------------------------------------------------------------
#define BR 128
#define BCt 32
#define KPAD 68   // padded row to spread smem banks on stores

__global__ __launch_bounds__(128) void attn_kernel(void)
{
    const int bh = blockIdx.x;        // 0..B*H-1
    const int qtile = blockIdx.y;     // 0..T/BR-1
    const int b = bh / Hc;
    const int h = bh % Hc;
    const int q0 = qtile * BR;
    const int tid = threadIdx.x;
    const int qi = q0 + tid;          // this thread's query index

    const float* base = g_qkv + (size_t)b * Tc * QKV_COLS;

    // Load q row (scaled by 1/sqrt(hd) = 0.125)
    float q[HDc];
    {
        const float* qptr = base + (size_t)qi * QKV_COLS + h * HDc;
#pragma unroll
        for (int d = 0; d < HDc; d += 4) {
            float4 v = *(const float4*)(qptr + d);
            q[d + 0] = v.x * 0.125f; q[d + 1] = v.y * 0.125f;
            q[d + 2] = v.z * 0.125f; q[d + 3] = v.w * 0.125f;
        }
    }

    float O[HDc];
#pragma unroll
    for (int d = 0; d < HDc; d++) O[d] = 0.0f;
    float m = -1e30f, l = 0.0f;

    __shared__ float Ks[BCt][KPAD];
    __shared__ float Vs[BCt][KPAD];

    const int kv_end = q0 + BR;   // exclusive: last key any query in tile can see

    for (int kv0 = 0; kv0 < kv_end; kv0 += BCt) {
        // Load K/V tile: 32 rows x 64 floats each; 4 threads per row
        {
            const int r = tid >> 2;            // 0..31
            const int c = (tid & 3) * 16;      // 0,16,32,48
            const float* kp = base + (size_t)(kv0 + r) * QKV_COLS + Cc + h * HDc + c;
            const float* vp = kp + Cc;
#pragma unroll
            for (int i = 0; i < 16; i += 4) {
                *(float4*)(&Ks[r][c + i]) = *(const float4*)(kp + i);
                *(float4*)(&Vs[r][c + i]) = *(const float4*)(vp + i);
            }
        }
        __syncthreads();

        // Scores for this tile
        float s[BCt];
#pragma unroll 4
        for (int j = 0; j < BCt; j++) {
            float a0 = 0.f, a1 = 0.f, a2 = 0.f, a3 = 0.f;
#pragma unroll
            for (int d = 0; d < HDc; d += 4) {
                float4 kk = *(const float4*)(&Ks[j][d]);
                a0 += q[d + 0] * kk.x;
                a1 += q[d + 1] * kk.y;
                a2 += q[d + 2] * kk.z;
                a3 += q[d + 3] * kk.w;
            }
            float sc = (a0 + a1) + (a2 + a3);
            s[j] = (kv0 + j <= qi) ? sc : -1e30f;
        }

        // Online softmax update
        float mt = m;
#pragma unroll
        for (int j = 0; j < BCt; j++) mt = fmaxf(mt, s[j]);
        const float scale = __expf(m - mt);
        float lsum = 0.0f;
#pragma unroll
        for (int j = 0; j < BCt; j++) {
            float p = __expf(s[j] - mt);
            s[j] = p;
            lsum += p;
        }
        m = mt;
        l = l * scale + lsum;
#pragma unroll
        for (int d = 0; d < HDc; d++) O[d] *= scale;

        // O += P @ V
#pragma unroll 4
        for (int j = 0; j < BCt; j++) {
            const float p = s[j];
#pragma unroll
            for (int d = 0; d < HDc; d += 4) {
                float4 vv = *(const float4*)(&Vs[j][d]);
                O[d + 0] += p * vv.x;
                O[d + 1] += p * vv.y;
                O[d + 2] += p * vv.z;
                O[d + 3] += p * vv.w;
            }
        }
        __syncthreads();
    }

    // Write y[b, qi, h*64 + d]
    const float inv = 1.0f / l;
    float* yp = g_y + (size_t)(b * Tc + qi) * Cc + h * HDc;
#pragma unroll
    for (int d = 0; d < HDc; d += 4) {
        float4 o;
        o.x = O[d + 0] * inv; o.y = O[d + 1] * inv;
        o.z = O[d + 2] * inv; o.w = O[d + 3] * inv;
        *(float4*)(yp + d) = o;
    }
}

// Wrapper kernels that use the device-global scratch (so host never needs
// symbol addresses).
__global__ __launch_bounds__(256) void qkv_gemm_wrap(
    const float* __restrict__ x, const float* __restrict__ w_attn,
    const float* __restrict__ b_attn);
__global__ __launch_bounds__(256) void proj_gemm_wrap(
    const float* __restrict__ w_proj, const float* __restrict__ b_proj,
    float* __restrict__ out);

// Reuse the sgemm body via device functions would duplicate code; instead,
// just take the scratch pointers as kernel arguments obtained in device code.
// Simpler: small launcher kernels are unnecessary — pass g_qkv/g_y via
// separate entry kernels that forward to the same __device__ logic.
// To keep things simple we instead instantiate sgemm twice with pointers
// resolved on the device side through these thin wrappers:

__device__ __forceinline__ float* qkv_ptr() { return g_qkv; }
__device__ __forceinline__ float* y_ptr()   { return g_y; }

__global__ __launch_bounds__(256) void sgemm_qkv(
    const float* __restrict__ A, const float* __restrict__ W,
    const float* __restrict__ bias)
{
    // duplicate of sgemm_nt_bias with C = g_qkv, M=4096, N=3072, K=1024
    __shared__ float As[BKK][BM];
    __shared__ float Bs[BKK][BN];
    const int K = Cc, N = QKV_COLS;
    float* C = qkv_ptr();

    const int tid = threadIdx.x;
    const int brow = blockIdx.y * BM;
    const int bcol = blockIdx.x * BN;
    const int ty = tid >> 4;
    const int tx = tid & 15;
    const int lr = tid >> 1;
    const int lc = (tid & 1) * 4;

    const float* Aptr = A + (size_t)(brow + lr) * K + lc;
    const float* Wptr = W + (size_t)(bcol + lr) * K + lc;

    float acc[8][8];
#pragma unroll
    for (int i = 0; i < 8; i++)
#pragma unroll
        for (int j = 0; j < 8; j++) acc[i][j] = 0.0f;

    for (int k0 = 0; k0 < K; k0 += BKK) {
        float4 a4 = *(const float4*)(Aptr + k0);
        float4 w4 = *(const float4*)(Wptr + k0);
        As[lc + 0][lr] = a4.x; As[lc + 1][lr] = a4.y;
        As[lc + 2][lr] = a4.z; As[lc + 3][lr] = a4.w;
        Bs[lc + 0][lr] = w4.x; Bs[lc + 1][lr] = w4.y;
        Bs[lc + 2][lr] = w4.z; Bs[lc + 3][lr] = w4.w;
        __syncthreads();
#pragma unroll
        for (int k = 0; k < BKK; k++) {
            float ar[8], br[8];
            float4 a0 = *(const float4*)(&As[k][ty * 8]);
            float4 a1 = *(const float4*)(&As[k][ty * 8 + 4]);
            float4 b0 = *(const float4*)(&Bs[k][tx * 8]);
            float4 b1 = *(const float4*)(&Bs[k][tx * 8 + 4]);
            ar[0] = a0.x; ar[1] = a0.y; ar[2] = a0.z; ar[3] = a0.w;
            ar[4] = a1.x; ar[5] = a1.y; ar[6] = a1.z; ar[7] = a1.w;
            br[0] = b0.x; br[1] = b0.y; br[2] = b0.z; br[3] = b0.w;
            br[4] = b1.x; br[5] = b1.y; br[6] = b1.z; br[7] = b1.w;
#pragma unroll
            for (int i = 0; i < 8; i++)
#pragma unroll
                for (int j = 0; j < 8; j++)
                    acc[i][j] += ar[i] * br[j];
        }
        __syncthreads();
    }
#pragma unroll
    for (int i = 0; i < 8; i++) {
        float* Crow = C + (size_t)(brow + ty * 8 + i) * N + bcol + tx * 8;
#pragma unroll
        for (int j = 0; j < 8; j += 4) {
            float4 o;
            o.x = acc[i][j + 0] + bias[bcol + tx * 8 + j + 0];
            o.y = acc[i][j + 1] + bias[bcol + tx * 8 + j + 1];
            o.z = acc[i][j + 2] + bias[bcol + tx * 8 + j + 2];
            o.w = acc[i][j + 3] + bias[bcol + tx * 8 + j + 3];
            *(float4*)(Crow + j) = o;
        }
    }
}

__global__ __launch_bounds__(256) void sgemm_proj(
    const float* __restrict__ W, const float* __restrict__ bias,
    float* __restrict__ C)
{
    // A = g_y, M=4096, N=1024, K=1024
    __shared__ float As[BKK][BM];
    __shared__ float Bs[BKK][BN];
    const int K = Cc, N = Cc;
    const float* A = y_ptr();

    const int tid = threadIdx.x;
    const int brow = blockIdx.y * BM;
    const int bcol = blockIdx.x * BN;
    const int ty = tid >> 4;
    const int tx = tid & 15;
    const int lr = tid >> 1;
    const int lc = (tid & 1) * 4;

    const float* Aptr = A + (size_t)(brow + lr) * K + lc;
    const float* Wptr = W + (size_t)(bcol + lr) * K + lc;

    float acc[8][8];
#pragma unroll
    for (int i = 0; i < 8; i++)
#pragma unroll
        for (int j = 0; j < 8; j++) acc[i][j] = 0.0f;

    for (int k0 = 0; k0 < K; k0 += BKK) {
        float4 a4 = *(const float4*)(Aptr + k0);
        float4 w4 = *(const float4*)(Wptr + k0);
        As[lc + 0][lr] = a4.x; As[lc + 1][lr] = a4.y;
        As[lc + 2][lr] = a4.z; As[lc + 3][lr] = a4.w;
        Bs[lc + 0][lr] = w4.x; Bs[lc + 1][lr] = w4.y;
        Bs[lc + 2][lr] = w4.z; Bs[lc + 3][lr] = w4.w;
        __syncthreads();
#pragma unroll
        for (int k = 0; k < BKK; k++) {
            float ar[8], br[8];
            float4 a0 = *(const float4*)(&As[k][ty * 8]);
            float4 a1 = *(const float4*)(&As[k][ty * 8 + 4]);
            float4 b0 = *(const float4*)(&Bs[k][tx * 8]);
            float4 b1 = *(const float4*)(&Bs[k][tx * 8 + 4]);
            ar[0] = a0.x; ar[1] = a0.y; ar[2] = a0.z; ar[3] = a0.w;
            ar[4] = a1.x; ar[5] = a1.y; ar[6] = a1.z; ar[7] = a1.w;
            br[0] = b0.x; br[1] = b0.y; br[2] = b0.z; br[3] = b0.w;
            br[4] = b1.x; br[5] = b1.y; br[6] = b1.z; br[7] = b1.w;
#pragma unroll
            for (int i = 0; i < 8; i++)
#pragma unroll
                for (int j = 0; j < 8; j++)
                    acc[i][j] += ar[i] * br[j];
        }
        __syncthreads();
    }
#pragma unroll
    for (int i = 0; i < 8; i++) {
        float* Crow = C + (size_t)(brow + ty * 8 + i) * N + bcol + tx * 8;
#pragma unroll
        for (int j = 0; j < 8; j += 4) {
            float4 o;
            o.x = acc[i][j + 0] + bias[bcol + tx * 8 + j + 0];
            o.y = acc[i][j + 1] + bias[bcol + tx * 8 + j + 1];
            o.z = acc[i][j + 2] + bias[bcol + tx * 8 + j + 2];
            o.w = acc[i][j + 3] + bias[bcol + tx * 8 + j + 3];
            *(float4*)(Crow + j) = o;
        }
    }
}

extern "C" void kernel_launch(void* const* d_in, const int* in_sizes, int n_in,
                              void* d_out, int out_size)
{
    const float* x      = (const float*)d_in[0];  // [B,T,C]
    const float* w_attn = (const float*)d_in[1];  // [3C,C]
    const float* b_attn = (const float*)d_in[2];  // [3C]
    const float* w_proj = (const float*)d_in[3];  // [C,C]
    const float* b_proj = (const float*)d_in[4];  // [C]
    float* out = (float*)d_out;                   // [B,T,C]

    // 1) QKV projection: [4096,1024] x [1024,3072] -> g_qkv
    {
        dim3 grid(QKV_COLS / BN, M_ROWS / BM);
        sgemm_qkv<<<grid, 256>>>(x, w_attn, b_attn);
    }
    // 2) Causal flash attention -> g_y
    {
        dim3 grid(Bc * Hc, Tc / BR);
        attn_kernel<<<grid, 128>>>();
    }
    // 3) Output projection: [4096,1024] x [1024,1024] -> out
    {
        dim3 grid(Cc / BN, M_ROWS / BM);
        sgemm_proj<<<grid, 256>>>(w_proj, b_proj, out);
    }
}

// round 2
// speedup vs baseline: 1.4173x; 1.4173x over previous
#include <cuda_runtime.h>
#include <math.h>

// Problem constants
#define Bc 2
#define Tc 2048
#define Cc 1024
#define Hc 16
#define HDc 64
#define M_ROWS (Bc * Tc)            // 4096
#define QKV_COLS (3 * Cc)           // 3072

// Scratch (device globals: no allocation allowed in kernel_launch)
__device__ float g_qkv[(size_t)M_ROWS * QKV_COLS];   // [B*T, 3C]
__device__ float g_y[(size_t)M_ROWS * Cc];           // [B*T, C]

// ---------------------------------------------------------------------------
// TF32 tensor-core GEMM: C[m,n] = sum_k A[m,k]*W[n,k] + bias[n]
// A:[M,K] row-major, W:[N,K] row-major. Block tile 128x128, KTILE=16,
// double-buffered smem, 8 warps, warp tile 64x32 (4x4 m16n8k8 frags).
// ---------------------------------------------------------------------------
#define KT 16
#define SROW 20   // smem row stride in words (16 + 4 pad): frag LDS conflict-free

__device__ __forceinline__ unsigned f2tf(float x) {
    unsigned y;
    asm("cvt.rna.tf32.f32 %0, %1;" : "=r"(y) : "f"(x));
    return y;
}

__device__ __forceinline__ void mma_tf32(float c[4], const unsigned a[4], const unsigned b[2]) {
    asm volatile(
        "mma.sync.aligned.m16n8k8.row.col.f32.tf32.tf32.f32 "
        "{%0,%1,%2,%3}, {%4,%5,%6,%7}, {%8,%9}, {%0,%1,%2,%3};\n"
        : "+f"(c[0]), "+f"(c[1]), "+f"(c[2]), "+f"(c[3])
        : "r"(a[0]), "r"(a[1]), "r"(a[2]), "r"(a[3]), "r"(b[0]), "r"(b[1]));
}

__device__ __forceinline__ void gemm_tf32_body(
    const float* __restrict__ A, const float* __restrict__ Wt,
    const float* __restrict__ bias, float* __restrict__ C,
    int N, int K)
{
    __shared__ unsigned As[2][128 * SROW];
    __shared__ unsigned Bs[2][128 * SROW];

    const int tid  = threadIdx.x;
    const int lane = tid & 31;
    const int g    = lane >> 2;        // 0..7
    const int t4   = lane & 3;         // 0..3
    const int warp = tid >> 5;         // 0..7
    const int wm   = (warp >> 2) * 64; // 0 or 64
    const int wn   = (warp & 3) * 32;  // 0,32,64,96
    const int brow = blockIdx.y * 128;
    const int bcol = blockIdx.x * 128;

    // Staging mapping: thread -> row lr (0..127), k-offset lk (0 or 8)
    const int lr = tid >> 1;
    const int lk = (tid & 1) * 8;

    const float* Ap = A  + (size_t)(brow + lr) * K + lk;
    const float* Wp = Wt + (size_t)(bcol + lr) * K + lk;

    float acc[4][4][4];
#pragma unroll
    for (int f = 0; f < 4; f++)
#pragma unroll
        for (int e = 0; e < 4; e++)
#pragma unroll
            for (int i = 0; i < 4; i++) acc[f][e][i] = 0.0f;

    float4 pa0, pa1, pb0, pb1;

    // Prime tile 0
    pa0 = *(const float4*)(Ap);     pa1 = *(const float4*)(Ap + 4);
    pb0 = *(const float4*)(Wp);     pb1 = *(const float4*)(Wp + 4);
    {
        unsigned* ad = &As[0][lr * SROW + lk];
        unsigned* bd = &Bs[0][lr * SROW + lk];
        uint4 u;
        u.x = f2tf(pa0.x); u.y = f2tf(pa0.y); u.z = f2tf(pa0.z); u.w = f2tf(pa0.w);
        *(uint4*)(ad) = u;
        u.x = f2tf(pa1.x); u.y = f2tf(pa1.y); u.z = f2tf(pa1.z); u.w = f2tf(pa1.w);
        *(uint4*)(ad + 4) = u;
        u.x = f2tf(pb0.x); u.y = f2tf(pb0.y); u.z = f2tf(pb0.z); u.w = f2tf(pb0.w);
        *(uint4*)(bd) = u;
        u.x = f2tf(pb1.x); u.y = f2tf(pb1.y); u.z = f2tf(pb1.z); u.w = f2tf(pb1.w);
        *(uint4*)(bd + 4) = u;
    }
    __syncthreads();

    const int NT = K / KT;
    for (int t = 0; t < NT; t++) {
        const int cur = t & 1;
        const int nxt = 1 - cur;

        // Prefetch next tile from global (consumed after compute)
        if (t + 1 < NT) {
            const float* Ap2 = Ap + (size_t)(t + 1) * KT;
            const float* Wp2 = Wp + (size_t)(t + 1) * KT;
            pa0 = *(const float4*)(Ap2);  pa1 = *(const float4*)(Ap2 + 4);
            pb0 = *(const float4*)(Wp2);  pb1 = *(const float4*)(Wp2 + 4);
        }

        // Compute 2 k8-steps from current buffer
#pragma unroll
        for (int kk = 0; kk < 2; kk++) {
            const int kb = kk * 8;
            unsigned af[4][4], bf[4][2];
#pragma unroll
            for (int f = 0; f < 4; f++) {
                const int r0 = wm + f * 16 + g;
                af[f][0] = As[cur][r0 * SROW + kb + t4];
                af[f][1] = As[cur][(r0 + 8) * SROW + kb + t4];
                af[f][2] = As[cur][r0 * SROW + kb + t4 + 4];
                af[f][3] = As[cur][(r0 + 8) * SROW + kb + t4 + 4];
            }
#pragma unroll
            for (int e = 0; e < 4; e++) {
                const int c0 = wn + e * 8 + g;
                bf[e][0] = Bs[cur][c0 * SROW + kb + t4];
                bf[e][1] = Bs[cur][c0 * SROW + kb + t4 + 4];
            }
#pragma unroll
            for (int f = 0; f < 4; f++)
#pragma unroll
                for (int e = 0; e < 4; e++)
                    mma_tf32(acc[f][e], af[f], bf[e]);
        }

        // Stage next tile into the other buffer
        if (t + 1 < NT) {
            unsigned* ad = &As[nxt][lr * SROW + lk];
            unsigned* bd = &Bs[nxt][lr * SROW + lk];
            uint4 u;
            u.x = f2tf(pa0.x); u.y = f2tf(pa0.y); u.z = f2tf(pa0.z); u.w = f2tf(pa0.w);
            *(uint4*)(ad) = u;
            u.x = f2tf(pa1.x); u.y = f2tf(pa1.y); u.z = f2tf(pa1.z); u.w = f2tf(pa1.w);
            *(uint4*)(ad + 4) = u;
            u.x = f2tf(pb0.x); u.y = f2tf(pb0.y); u.z = f2tf(pb0.z); u.w = f2tf(pb0.w);
            *(uint4*)(bd) = u;
            u.x = f2tf(pb1.x); u.y = f2tf(pb1.y); u.z = f2tf(pb1.z); u.w = f2tf(pb1.w);
            *(uint4*)(bd + 4) = u;
        }
        __syncthreads();
    }

    // Epilogue: acc -> C with bias
#pragma unroll
    for (int f = 0; f < 4; f++) {
        const int r0 = brow + wm + f * 16 + g;
#pragma unroll
        for (int e = 0; e < 4; e++) {
            const int c = bcol + wn + e * 8 + t4 * 2;
            const float b0v = bias[c];
            const float b1v = bias[c + 1];
            float2 o0, o1;
            o0.x = acc[f][e][0] + b0v;  o0.y = acc[f][e][1] + b1v;
            o1.x = acc[f][e][2] + b0v;  o1.y = acc[f][e][3] + b1v;
            *(float2*)(&C[(size_t)r0 * N + c]) = o0;
            *(float2*)(&C[(size_t)(r0 + 8) * N + c]) = o1;
        }
    }
}

__global__ __launch_bounds__(256) void qkv_tf32(
    const float* __restrict__ x, const float* __restrict__ w,
    const float* __restrict__ b)
{
    gemm_tf32_body(x, w, b, g_qkv, QKV_COLS, Cc);
}

__global__ __launch_bounds__(256) void proj_tf32(
    const float* __restrict__ w, const float* __restrict__ b,
    float* __restrict__ out)
{
    gemm_tf32_body(g_y, w, b, out, Cc, Cc);
}

// ---------------------------------------------------------------------------
// Flash attention (causal), fp32, one thread per query row. (unchanged R0)
// ---------------------------------------------------------------------------
#define BR 128
#define BCt 32
#define KPAD 68

__global__ __launch_bounds__(128) void attn_kernel(void)
{
    const int bh = blockIdx.x;
    const int qtile = blockIdx.y;
    const int b = bh / Hc;
    const int h = bh % Hc;
    const int q0 = qtile * BR;
    const int tid = threadIdx.x;
    const int qi = q0 + tid;

    const float* base = g_qkv + (size_t)b * Tc * QKV_COLS;

    float q[HDc];
    {
        const float* qptr = base + (size_t)qi * QKV_COLS + h * HDc;
#pragma unroll
        for (int d = 0; d < HDc; d += 4) {
            float4 v = *(const float4*)(qptr + d);
            q[d + 0] = v.x * 0.125f; q[d + 1] = v.y * 0.125f;
            q[d + 2] = v.z * 0.125f; q[d + 3] = v.w * 0.125f;
        }
    }

    float O[HDc];
#pragma unroll
    for (int d = 0; d < HDc; d++) O[d] = 0.0f;
    float m = -1e30f, l = 0.0f;

    __shared__ float Ks[BCt][KPAD];
    __shared__ float Vs[BCt][KPAD];

    const int kv_end = q0 + BR;

    for (int kv0 = 0; kv0 < kv_end; kv0 += BCt) {
        {
            const int r = tid >> 2;
            const int c = (tid & 3) * 16;
            const float* kp = base + (size_t)(kv0 + r) * QKV_COLS + Cc + h * HDc + c;
            const float* vp = kp + Cc;
#pragma unroll
            for (int i = 0; i < 16; i += 4) {
                *(float4*)(&Ks[r][c + i]) = *(const float4*)(kp + i);
                *(float4*)(&Vs[r][c + i]) = *(const float4*)(vp + i);
            }
        }
        __syncthreads();

        float s[BCt];
#pragma unroll 4
        for (int j = 0; j < BCt; j++) {
            float a0 = 0.f, a1 = 0.f, a2 = 0.f, a3 = 0.f;
#pragma unroll
            for (int d = 0; d < HDc; d += 4) {
                float4 kk = *(const float4*)(&Ks[j][d]);
                a0 += q[d + 0] * kk.x;
                a1 += q[d + 1] * kk.y;
                a2 += q[d + 2] * kk.z;
                a3 += q[d + 3] * kk.w;
            }
            float sc = (a0 + a1) + (a2 + a3);
            s[j] = (kv0 + j <= qi) ? sc : -1e30f;
        }

        float mt = m;
#pragma unroll
        for (int j = 0; j < BCt; j++) mt = fmaxf(mt, s[j]);
        const float scale = __expf(m - mt);
        float lsum = 0.0f;
#pragma unroll
        for (int j = 0; j < BCt; j++) {
            float p = __expf(s[j] - mt);
            s[j] = p;
            lsum += p;
        }
        m = mt;
        l = l * scale + lsum;
#pragma unroll
        for (int d = 0; d < HDc; d++) O[d] *= scale;

#pragma unroll 4
        for (int j = 0; j < BCt; j++) {
            const float p = s[j];
#pragma unroll
            for (int d = 0; d < HDc; d += 4) {
                float4 vv = *(const float4*)(&Vs[j][d]);
                O[d + 0] += p * vv.x;
                O[d + 1] += p * vv.y;
                O[d + 2] += p * vv.z;
                O[d + 3] += p * vv.w;
            }
        }
        __syncthreads();
    }

    const float inv = 1.0f / l;
    float* yp = g_y + (size_t)(b * Tc + qi) * Cc + h * HDc;
#pragma unroll
    for (int d = 0; d < HDc; d += 4) {
        float4 o;
        o.x = O[d + 0] * inv; o.y = O[d + 1] * inv;
        o.z = O[d + 2] * inv; o.w = O[d + 3] * inv;
        *(float4*)(yp + d) = o;
    }
}

extern "C" void kernel_launch(void* const* d_in, const int* in_sizes, int n_in,
                              void* d_out, int out_size)
{
    const float* x      = (const float*)d_in[0];
    const float* w_attn = (const float*)d_in[1];
    const float* b_attn = (const float*)d_in[2];
    const float* w_proj = (const float*)d_in[3];
    const float* b_proj = (const float*)d_in[4];
    float* out = (float*)d_out;

    {
        dim3 grid(QKV_COLS / 128, M_ROWS / 128);
        qkv_tf32<<<grid, 256>>>(x, w_attn, b_attn);
    }
    {
        dim3 grid(Bc * Hc, Tc / BR);
        attn_kernel<<<grid, 128>>>();
    }
    {
        dim3 grid(Cc / 128, M_ROWS / 128);
        proj_tf32<<<grid, 256>>>(w_proj, b_proj, out);
    }
}

// round 3
// speedup vs baseline: 2.4359x; 1.7187x over previous
#include <cuda_runtime.h>
#include <math.h>

// Problem constants
#define Bc 2
#define Tc 2048
#define Cc 1024
#define Hc 16
#define HDc 64
#define M_ROWS (Bc * Tc)            // 4096
#define QKV_COLS (3 * Cc)           // 3072

// Scratch (device globals)
__device__ float g_qkv[(size_t)M_ROWS * QKV_COLS];   // [B*T, 3C]
__device__ float g_y[(size_t)M_ROWS * Cc];           // [B*T, C]

__device__ __forceinline__ unsigned f2tf(float x) {
    unsigned y;
    asm("cvt.rna.tf32.f32 %0, %1;" : "=r"(y) : "f"(x));
    return y;
}

__device__ __forceinline__ void mma_tf32(float c[4], const unsigned a[4], const unsigned b[2]) {
    asm volatile(
        "mma.sync.aligned.m16n8k8.row.col.f32.tf32.tf32.f32 "
        "{%0,%1,%2,%3}, {%4,%5,%6,%7}, {%8,%9}, {%0,%1,%2,%3};\n"
        : "+f"(c[0]), "+f"(c[1]), "+f"(c[2]), "+f"(c[3])
        : "r"(a[0]), "r"(a[1]), "r"(a[2]), "r"(a[3]), "r"(b[0]), "r"(b[1]));
}

// ---------------------------------------------------------------------------
// TF32 GEMM (unchanged from R1): C = A @ W^T + bias
// ---------------------------------------------------------------------------
#define KT 16
#define SROW 20

__device__ __forceinline__ void gemm_tf32_body(
    const float* __restrict__ A, const float* __restrict__ Wt,
    const float* __restrict__ bias, float* __restrict__ C,
    int N, int K)
{
    __shared__ unsigned As[2][128 * SROW];
    __shared__ unsigned Bs[2][128 * SROW];

    const int tid  = threadIdx.x;
    const int lane = tid & 31;
    const int g    = lane >> 2;
    const int t4   = lane & 3;
    const int warp = tid >> 5;
    const int wm   = (warp >> 2) * 64;
    const int wn   = (warp & 3) * 32;
    const int brow = blockIdx.y * 128;
    const int bcol = blockIdx.x * 128;

    const int lr = tid >> 1;
    const int lk = (tid & 1) * 8;

    const float* Ap = A  + (size_t)(brow + lr) * K + lk;
    const float* Wp = Wt + (size_t)(bcol + lr) * K + lk;

    float acc[4][4][4];
#pragma unroll
    for (int f = 0; f < 4; f++)
#pragma unroll
        for (int e = 0; e < 4; e++)
#pragma unroll
            for (int i = 0; i < 4; i++) acc[f][e][i] = 0.0f;

    float4 pa0, pa1, pb0, pb1;
    pa0 = *(const float4*)(Ap);  pa1 = *(const float4*)(Ap + 4);
    pb0 = *(const float4*)(Wp);  pb1 = *(const float4*)(Wp + 4);
    {
        unsigned* ad = &As[0][lr * SROW + lk];
        unsigned* bd = &Bs[0][lr * SROW + lk];
        uint4 u;
        u.x = f2tf(pa0.x); u.y = f2tf(pa0.y); u.z = f2tf(pa0.z); u.w = f2tf(pa0.w);
        *(uint4*)(ad) = u;
        u.x = f2tf(pa1.x); u.y = f2tf(pa1.y); u.z = f2tf(pa1.z); u.w = f2tf(pa1.w);
        *(uint4*)(ad + 4) = u;
        u.x = f2tf(pb0.x); u.y = f2tf(pb0.y); u.z = f2tf(pb0.z); u.w = f2tf(pb0.w);
        *(uint4*)(bd) = u;
        u.x = f2tf(pb1.x); u.y = f2tf(pb1.y); u.z = f2tf(pb1.z); u.w = f2tf(pb1.w);
        *(uint4*)(bd + 4) = u;
    }
    __syncthreads();

    const int NT = K / KT;
    for (int t = 0; t < NT; t++) {
        const int cur = t & 1;
        const int nxt = 1 - cur;

        if (t + 1 < NT) {
            const float* Ap2 = Ap + (size_t)(t + 1) * KT;
            const float* Wp2 = Wp + (size_t)(t + 1) * KT;
            pa0 = *(const float4*)(Ap2);  pa1 = *(const float4*)(Ap2 + 4);
            pb0 = *(const float4*)(Wp2);  pb1 = *(const float4*)(Wp2 + 4);
        }

#pragma unroll
        for (int kk = 0; kk < 2; kk++) {
            const int kb = kk * 8;
            unsigned af[4][4], bf[4][2];
#pragma unroll
            for (int f = 0; f < 4; f++) {
                const int r0 = wm + f * 16 + g;
                af[f][0] = As[cur][r0 * SROW + kb + t4];
                af[f][1] = As[cur][(r0 + 8) * SROW + kb + t4];
                af[f][2] = As[cur][r0 * SROW + kb + t4 + 4];
                af[f][3] = As[cur][(r0 + 8) * SROW + kb + t4 + 4];
            }
#pragma unroll
            for (int e = 0; e < 4; e++) {
                const int c0 = wn + e * 8 + g;
                bf[e][0] = Bs[cur][c0 * SROW + kb + t4];
                bf[e][1] = Bs[cur][c0 * SROW + kb + t4 + 4];
            }
#pragma unroll
            for (int f = 0; f < 4; f++)
#pragma unroll
                for (int e = 0; e < 4; e++)
                    mma_tf32(acc[f][e], af[f], bf[e]);
        }

        if (t + 1 < NT) {
            unsigned* ad = &As[nxt][lr * SROW + lk];
            unsigned* bd = &Bs[nxt][lr * SROW + lk];
            uint4 u;
            u.x = f2tf(pa0.x); u.y = f2tf(pa0.y); u.z = f2tf(pa0.z); u.w = f2tf(pa0.w);
            *(uint4*)(ad) = u;
            u.x = f2tf(pa1.x); u.y = f2tf(pa1.y); u.z = f2tf(pa1.z); u.w = f2tf(pa1.w);
            *(uint4*)(ad + 4) = u;
            u.x = f2tf(pb0.x); u.y = f2tf(pb0.y); u.z = f2tf(pb0.z); u.w = f2tf(pb0.w);
            *(uint4*)(bd) = u;
            u.x = f2tf(pb1.x); u.y = f2tf(pb1.y); u.z = f2tf(pb1.z); u.w = f2tf(pb1.w);
            *(uint4*)(bd + 4) = u;
        }
        __syncthreads();
    }

#pragma unroll
    for (int f = 0; f < 4; f++) {
        const int r0 = brow + wm + f * 16 + g;
#pragma unroll
        for (int e = 0; e < 4; e++) {
            const int c = bcol + wn + e * 8 + t4 * 2;
            const float b0v = bias[c];
            const float b1v = bias[c + 1];
            float2 o0, o1;
            o0.x = acc[f][e][0] + b0v;  o0.y = acc[f][e][1] + b1v;
            o1.x = acc[f][e][2] + b0v;  o1.y = acc[f][e][3] + b1v;
            *(float2*)(&C[(size_t)r0 * N + c]) = o0;
            *(float2*)(&C[(size_t)(r0 + 8) * N + c]) = o1;
        }
    }
}

__global__ __launch_bounds__(256) void qkv_tf32(
    const float* __restrict__ x, const float* __restrict__ w,
    const float* __restrict__ b)
{
    gemm_tf32_body(x, w, b, g_qkv, QKV_COLS, Cc);
}

__global__ __launch_bounds__(256) void proj_tf32(
    const float* __restrict__ w, const float* __restrict__ b,
    float* __restrict__ out)
{
    gemm_tf32_body(g_y, w, b, out, Cc, Cc);
}

// ---------------------------------------------------------------------------
// Tensor-core causal flash attention (tf32 mma).
// CTA: 128 threads (4 warps) = one 64-row query tile of one (b,h).
// Each warp owns 16 query rows. Key tiles of 64, K/V staged in smem.
// Ks stride 68 (conflict-free for K B-frags / Q & P A-frags),
// Vs stride 72 (conflict-free for V B-frags).
// P reuses the Ks buffer after S is computed.
// ---------------------------------------------------------------------------
#define KSTR 68
#define VSTR 72

__global__ __launch_bounds__(128) void attn_tc(void)
{
    const int bh  = blockIdx.x;
    const int qt  = blockIdx.y;
    const int b   = bh >> 4;
    const int h   = bh & 15;
    const int q0  = qt * 64;
    const int tid = threadIdx.x;
    const int lane = tid & 31;
    const int warp = tid >> 5;
    const int g   = lane >> 2;
    const int t4  = lane & 3;

    __shared__ unsigned Ks[64 * KSTR];   // K tile; later P tile
    __shared__ unsigned Vs[64 * VSTR];   // V tile

    const float* base = g_qkv + (size_t)b * Tc * QKV_COLS;

    // ---- Stage Q (pre-scaled) into Ks, pull A-frags to registers ----
    {
        const int r  = tid >> 1;
        const int c0 = (tid & 1) * 32;
        const float* qp = base + (size_t)(q0 + r) * QKV_COLS + h * HDc + c0;
        unsigned* dst = &Ks[r * KSTR + c0];
#pragma unroll
        for (int i = 0; i < 32; i += 4) {
            float4 v = *(const float4*)(qp + i);
            uint4 u;
            u.x = f2tf(v.x * 0.125f); u.y = f2tf(v.y * 0.125f);
            u.z = f2tf(v.z * 0.125f); u.w = f2tf(v.w * 0.125f);
            *(uint4*)(dst + i) = u;
        }
    }
    __syncthreads();

    unsigned qf[8][4];
    {
        const int r0 = warp * 16 + g;
#pragma unroll
        for (int kb = 0; kb < 8; kb++) {
            qf[kb][0] = Ks[r0 * KSTR + kb * 8 + t4];
            qf[kb][1] = Ks[(r0 + 8) * KSTR + kb * 8 + t4];
            qf[kb][2] = Ks[r0 * KSTR + kb * 8 + t4 + 4];
            qf[kb][3] = Ks[(r0 + 8) * KSTR + kb * 8 + t4 + 4];
        }
    }
    __syncthreads();

    float O[8][4];
#pragma unroll
    for (int e = 0; e < 8; e++)
#pragma unroll
        for (int i = 0; i < 4; i++) O[e][i] = 0.0f;
    float m0 = -1e30f, m1 = -1e30f, l0 = 0.0f, l1 = 0.0f;

    const int r0w = warp * 16 + g;   // local row (c0/c1); +8 for c2/c3

    for (int kt = 0; kt <= qt; kt++) {
        const int kv0 = kt * 64;

        // ---- Stage K -> Ks, V -> Vs ----
        {
            const int r  = tid >> 1;
            const int c0 = (tid & 1) * 32;
            const float* kp = base + (size_t)(kv0 + r) * QKV_COLS + Cc + h * HDc + c0;
            const float* vp = kp + Cc;
            unsigned* kd = &Ks[r * KSTR + c0];
            unsigned* vd = &Vs[r * VSTR + c0];
#pragma unroll
            for (int i = 0; i < 32; i += 4) {
                float4 kv4 = *(const float4*)(kp + i);
                float4 vv4 = *(const float4*)(vp + i);
                uint4 u;
                u.x = f2tf(kv4.x); u.y = f2tf(kv4.y); u.z = f2tf(kv4.z); u.w = f2tf(kv4.w);
                *(uint4*)(kd + i) = u;
                u.x = f2tf(vv4.x); u.y = f2tf(vv4.y); u.z = f2tf(vv4.z); u.w = f2tf(vv4.w);
                *(uint4*)(vd + i) = u;
            }
        }
        __syncthreads();

        // ---- S = Q @ K^T (16x64 per warp) ----
        float S[8][4];
#pragma unroll
        for (int e = 0; e < 8; e++)
#pragma unroll
            for (int i = 0; i < 4; i++) S[e][i] = 0.0f;

#pragma unroll
        for (int kb = 0; kb < 8; kb++) {
#pragma unroll
            for (int e = 0; e < 8; e++) {
                unsigned bfr[2];
                const int j = e * 8 + g;
                bfr[0] = Ks[j * KSTR + kb * 8 + t4];
                bfr[1] = Ks[j * KSTR + kb * 8 + t4 + 4];
                mma_tf32(S[e], qf[kb], bfr);
            }
        }

        // ---- Causal mask (diagonal tile only) ----
        if (kt == qt) {
#pragma unroll
            for (int e = 0; e < 8; e++) {
                const int j = e * 8 + 2 * t4;
                if (j > r0w)         S[e][0] = -1e30f;
                if (j + 1 > r0w)     S[e][1] = -1e30f;
                if (j > r0w + 8)     S[e][2] = -1e30f;
                if (j + 1 > r0w + 8) S[e][3] = -1e30f;
            }
        }

        // ---- Online softmax ----
        float tm0 = -1e30f, tm1 = -1e30f;
#pragma unroll
        for (int e = 0; e < 8; e++) {
            tm0 = fmaxf(tm0, fmaxf(S[e][0], S[e][1]));
            tm1 = fmaxf(tm1, fmaxf(S[e][2], S[e][3]));
        }
        tm0 = fmaxf(tm0, __shfl_xor_sync(0xffffffffu, tm0, 1));
        tm0 = fmaxf(tm0, __shfl_xor_sync(0xffffffffu, tm0, 2));
        tm1 = fmaxf(tm1, __shfl_xor_sync(0xffffffffu, tm1, 1));
        tm1 = fmaxf(tm1, __shfl_xor_sync(0xffffffffu, tm1, 2));

        const float nm0 = fmaxf(m0, tm0);
        const float nm1 = fmaxf(m1, tm1);
        const float al0 = __expf(m0 - nm0);
        const float al1 = __expf(m1 - nm1);

        float ts0 = 0.0f, ts1 = 0.0f;
#pragma unroll
        for (int e = 0; e < 8; e++) {
            S[e][0] = __expf(S[e][0] - nm0);
            S[e][1] = __expf(S[e][1] - nm0);
            S[e][2] = __expf(S[e][2] - nm1);
            S[e][3] = __expf(S[e][3] - nm1);
            ts0 += S[e][0] + S[e][1];
            ts1 += S[e][2] + S[e][3];
        }
        ts0 += __shfl_xor_sync(0xffffffffu, ts0, 1);
        ts0 += __shfl_xor_sync(0xffffffffu, ts0, 2);
        ts1 += __shfl_xor_sync(0xffffffffu, ts1, 1);
        ts1 += __shfl_xor_sync(0xffffffffu, ts1, 2);

        l0 = l0 * al0 + ts0;
        l1 = l1 * al1 + ts1;
        m0 = nm0;
        m1 = nm1;

#pragma unroll
        for (int e = 0; e < 8; e++) {
            O[e][0] *= al0; O[e][1] *= al0;
            O[e][2] *= al1; O[e][3] *= al1;
        }

        __syncthreads();   // all warps done reading Ks (K); safe to overwrite with P

        // ---- Store P (tf32) into warp-private rows of Ks ----
        {
#pragma unroll
            for (int e = 0; e < 8; e++) {
                const int c = e * 8 + 2 * t4;
                uint2 u0, u1;
                u0.x = f2tf(S[e][0]); u0.y = f2tf(S[e][1]);
                u1.x = f2tf(S[e][2]); u1.y = f2tf(S[e][3]);
                *(uint2*)(&Ks[r0w * KSTR + c])       = u0;
                *(uint2*)(&Ks[(r0w + 8) * KSTR + c]) = u1;
            }
        }
        __syncwarp();

        // ---- O += P @ V ----
#pragma unroll
        for (int kb = 0; kb < 8; kb++) {
            unsigned af[4];
            af[0] = Ks[r0w * KSTR + kb * 8 + t4];
            af[1] = Ks[(r0w + 8) * KSTR + kb * 8 + t4];
            af[2] = Ks[r0w * KSTR + kb * 8 + t4 + 4];
            af[3] = Ks[(r0w + 8) * KSTR + kb * 8 + t4 + 4];
#pragma unroll
            for (int e = 0; e < 8; e++) {
                unsigned bfr[2];
                bfr[0] = Vs[(kb * 8 + t4) * VSTR + e * 8 + g];
                bfr[1] = Vs[(kb * 8 + t4 + 4) * VSTR + e * 8 + g];
                mma_tf32(O[e], af, bfr);
            }
        }
        __syncthreads();   // before next tile staging overwrites Ks/Vs
    }

    // ---- Epilogue: normalize and write y ----
    const float inv0 = 1.0f / l0;
    const float inv1 = 1.0f / l1;
    const int gr = q0 + r0w;
    float* yp0 = g_y + (size_t)(b * Tc + gr) * Cc + h * HDc;
    float* yp1 = g_y + (size_t)(b * Tc + gr + 8) * Cc + h * HDc;
#pragma unroll
    for (int e = 0; e < 8; e++) {
        const int c = e * 8 + 2 * t4;
        float2 o0, o1;
        o0.x = O[e][0] * inv0; o0.y = O[e][1] * inv0;
        o1.x = O[e][2] * inv1; o1.y = O[e][3] * inv1;
        *(float2*)(yp0 + c) = o0;
        *(float2*)(yp1 + c) = o1;
    }
}

extern "C" void kernel_launch(void* const* d_in, const int* in_sizes, int n_in,
                              void* d_out, int out_size)
{
    const float* x      = (const float*)d_in[0];
    const float* w_attn = (const float*)d_in[1];
    const float* b_attn = (const float*)d_in[2];
    const float* w_proj = (const float*)d_in[3];
    const float* b_proj = (const float*)d_in[4];
    float* out = (float*)d_out;

    {
        dim3 grid(QKV_COLS / 128, M_ROWS / 128);
        qkv_tf32<<<grid, 256>>>(x, w_attn, b_attn);
    }
    {
        dim3 grid(Bc * Hc, Tc / 64);
        attn_tc<<<grid, 128>>>();
    }
    {
        dim3 grid(Cc / 128, M_ROWS / 128);
        proj_tf32<<<grid, 256>>>(w_proj, b_proj, out);
    }
}